// round 5
// baseline (speedup 1.0000x reference)
#include <cuda_runtime.h>
#include <cuda_fp16.h>
#include <math.h>
#include <stdint.h>

#define BATCH 2
#define SEQ   8192
#define DM    1024
#define NH    16
#define DKH   64
#define MTOK  (BATCH*SEQ)
#define KVCH  32
#define CHSZ  (SEQ/KVCH)

// ---------------- scratch (static device globals; no allocations) ----------------
__device__ __half g_qh[(size_t)MTOK * DM];
__device__ __half g_kh[(size_t)MTOK * DM];
__device__ __half g_vh[(size_t)MTOK * DM];
__device__ __half g_ah[(size_t)MTOK * DM];
__device__ float g_kvpart[KVCH * 32 * DKH * DKH];
__device__ float g_kspart[KVCH * 32 * DKH];
__device__ float g_kv[32 * DKH * DKH];
__device__ float g_ks[32 * DKH];

// ---------------- helpers ---------------------------------------------------------
__device__ __forceinline__ uint32_t smem_u32(const void* p) {
    uint32_t a;
    asm("{ .reg .u64 t; cvta.to.shared.u64 t, %1; cvt.u32.u64 %0, t; }"
        : "=r"(a) : "l"(p));
    return a;
}

__device__ __forceinline__ uint32_t pack_h2(float x, float y) {
    __half2 h = __floats2half2_rn(x, y);
    return reinterpret_cast<uint32_t&>(h);
}

__device__ __forceinline__ void ldsm4(uint32_t& r0, uint32_t& r1, uint32_t& r2,
                                      uint32_t& r3, uint32_t a) {
    asm volatile("ldmatrix.sync.aligned.m8n8.x4.shared.b16 {%0,%1,%2,%3}, [%4];"
                 : "=r"(r0), "=r"(r1), "=r"(r2), "=r"(r3) : "r"(a));
}

__device__ __forceinline__ void ldsm4t(uint32_t& r0, uint32_t& r1, uint32_t& r2,
                                       uint32_t& r3, uint32_t a) {
    asm volatile("ldmatrix.sync.aligned.m8n8.x4.trans.shared.b16 {%0,%1,%2,%3}, [%4];"
                 : "=r"(r0), "=r"(r1), "=r"(r2), "=r"(r3) : "r"(a));
}

__device__ __forceinline__ void mma_f16(float c[4], const uint32_t a[4],
                                        uint32_t b0, uint32_t b1) {
    asm volatile(
        "mma.sync.aligned.m16n8k16.row.col.f32.f16.f16.f32 "
        "{%0,%1,%2,%3},{%4,%5,%6,%7},{%8,%9},{%0,%1,%2,%3};"
        : "+f"(c[0]), "+f"(c[1]), "+f"(c[2]), "+f"(c[3])
        : "r"(a[0]), "r"(a[1]), "r"(a[2]), "r"(a[3]), "r"(b0), "r"(b1));
}

// ---------------- fp16 GEMM (A fp32 in, half out): C = A*W^T + b (+elu+1) ---------
#define BM 128
#define BN 128
#define BK 32
#define SSTH 40
#define ATILE (BM*SSTH)
#define STG (2*ATILE)

__global__ void __launch_bounds__(256, 1)
gemm_p(const float* __restrict__ A, const float* __restrict__ W,
       const float* __restrict__ bias, __half* __restrict__ C, int fmap)
{
    __shared__ __align__(16) __half sh[2 * STG];

    const int t    = threadIdx.x;
    const int lane = t & 31, warp = t >> 5;
    const int g  = lane >> 2, tg = lane & 3;
    const int wm = (warp >> 2) * 64;
    const int wn = (warp & 3) * 32;

    const int lr = t >> 3;
    const int lv = t & 7;

    const float* Ag = A + (size_t)(blockIdx.y * BM + lr) * DM + lv * 4;
    const float* Wg = W + (size_t)(blockIdx.x * BN + lr) * DM + lv * 4;

    float c[4][4][4];
    #pragma unroll
    for (int i = 0; i < 4; i++)
        #pragma unroll
        for (int j = 0; j < 4; j++) {
            c[i][j][0] = 0.f; c[i][j][1] = 0.f; c[i][j][2] = 0.f; c[i][j][3] = 0.f;
        }

    const int sub = lane >> 3, r8 = lane & 7;
    const int aoff = (r8 + (sub & 1) * 8) * SSTH + (sub >> 1) * 8;
    const int boff = (r8 + (sub >> 1) * 8) * SSTH + (sub & 1) * 8;
    const uint32_t sbase = smem_u32(sh);
    const uint32_t aAddr0 = sbase + 2u * (uint32_t)(wm * SSTH + aoff);
    const uint32_t bAddr0 = sbase + 2u * (uint32_t)(ATILE + wn * SSTH + boff);

    float4 ra[4], rb[4];
    #pragma unroll
    for (int i = 0; i < 4; i++) ra[i] = *(const float4*)(Ag + (size_t)i * 32 * DM);
    #pragma unroll
    for (int i = 0; i < 4; i++) rb[i] = *(const float4*)(Wg + (size_t)i * 32 * DM);

    {
        __half* dst = sh;
        const int so = lr * SSTH + lv * 4;
        #pragma unroll
        for (int i = 0; i < 4; i++) {
            uint2 u; u.x = pack_h2(ra[i].x, ra[i].y); u.y = pack_h2(ra[i].z, ra[i].w);
            *(uint2*)&dst[so + i * 32 * SSTH] = u;
        }
        #pragma unroll
        for (int i = 0; i < 4; i++) {
            uint2 u; u.x = pack_h2(rb[i].x, rb[i].y); u.y = pack_h2(rb[i].z, rb[i].w);
            *(uint2*)&dst[ATILE + so + i * 32 * SSTH] = u;
        }
    }
    __syncthreads();

    const int NK = DM / BK;
    int stage = 0;
    for (int kt = 0; kt < NK; kt++) {
        if (kt + 1 < NK) {
            const float* Ap = Ag + (kt + 1) * BK;
            const float* Wp = Wg + (kt + 1) * BK;
            #pragma unroll
            for (int i = 0; i < 4; i++) ra[i] = *(const float4*)(Ap + (size_t)i * 32 * DM);
            #pragma unroll
            for (int i = 0; i < 4; i++) rb[i] = *(const float4*)(Wp + (size_t)i * 32 * DM);
        }

        const uint32_t stoff = (uint32_t)(stage * STG * 2);
        #pragma unroll
        for (int ks = 0; ks < 2; ks++) {
            const uint32_t kb2 = (uint32_t)(ks * 16 * 2);
            uint32_t af[4][4], bf[4][2];
            #pragma unroll
            for (int mt = 0; mt < 4; mt++)
                ldsm4(af[mt][0], af[mt][1], af[mt][2], af[mt][3],
                      aAddr0 + stoff + (uint32_t)(mt * 16 * SSTH * 2) + kb2);
            ldsm4(bf[0][0], bf[0][1], bf[1][0], bf[1][1], bAddr0 + stoff + kb2);
            ldsm4(bf[2][0], bf[2][1], bf[3][0], bf[3][1],
                  bAddr0 + stoff + (uint32_t)(16 * SSTH * 2) + kb2);
            #pragma unroll
            for (int mt = 0; mt < 4; mt++)
                #pragma unroll
                for (int nt = 0; nt < 4; nt++)
                    mma_f16(c[mt][nt], af[mt], bf[nt][0], bf[nt][1]);
        }

        if (kt + 1 < NK) {
            stage ^= 1;
            __half* dst = sh + stage * STG;
            const int so = lr * SSTH + lv * 4;
            #pragma unroll
            for (int i = 0; i < 4; i++) {
                uint2 u; u.x = pack_h2(ra[i].x, ra[i].y); u.y = pack_h2(ra[i].z, ra[i].w);
                *(uint2*)&dst[so + i * 32 * SSTH] = u;
            }
            #pragma unroll
            for (int i = 0; i < 4; i++) {
                uint2 u; u.x = pack_h2(rb[i].x, rb[i].y); u.y = pack_h2(rb[i].z, rb[i].w);
                *(uint2*)&dst[ATILE + so + i * 32 * SSTH] = u;
            }
        }
        __syncthreads();
    }

    const int rbase = blockIdx.y * BM + wm + g;
    const int cbase = blockIdx.x * BN + wn + tg * 2;
    #pragma unroll
    for (int mt = 0; mt < 4; mt++) {
        #pragma unroll
        for (int nt = 0; nt < 4; nt++) {
            const int col = cbase + nt * 8;
            const float bb0 = bias[col], bb1 = bias[col + 1];
            const int r0 = rbase + mt * 16;
            float v00 = c[mt][nt][0] + bb0;
            float v01 = c[mt][nt][1] + bb1;
            float v10 = c[mt][nt][2] + bb0;
            float v11 = c[mt][nt][3] + bb1;
            if (fmap) {
                v00 = v00 > 0.f ? v00 + 1.f : __expf(v00);
                v01 = v01 > 0.f ? v01 + 1.f : __expf(v01);
                v10 = v10 > 0.f ? v10 + 1.f : __expf(v10);
                v11 = v11 > 0.f ? v11 + 1.f : __expf(v11);
            }
            *(__half2*)&C[(size_t)r0 * DM + col]       = __floats2half2_rn(v00, v01);
            *(__half2*)&C[(size_t)(r0 + 8) * DM + col] = __floats2half2_rn(v10, v11);
        }
    }
}

// ---------------- fp16 GEMM (A half in, float out): C = A*W^T + b -----------------
__global__ void __launch_bounds__(256, 1)
gemm_o(const __half* __restrict__ A, const float* __restrict__ W,
       const float* __restrict__ bias, float* __restrict__ C)
{
    __shared__ __align__(16) __half sh[2 * STG];

    const int t    = threadIdx.x;
    const int lane = t & 31, warp = t >> 5;
    const int g  = lane >> 2, tg = lane & 3;
    const int wm = (warp >> 2) * 64;
    const int wn = (warp & 3) * 32;

    const int lr = t >> 3;
    const int lv = t & 7;

    // A half path: thread handles rows (t>>2) and (t>>2)+64, 8 halves at (t&3)*8
    const int lrA = t >> 2, lvA = t & 3;
    const __half* Ag = A + (size_t)(blockIdx.y * BM + lrA) * DM + lvA * 8;
    const float*  Wg = W + (size_t)(blockIdx.x * BN + lr) * DM + lv * 4;

    float c[4][4][4];
    #pragma unroll
    for (int i = 0; i < 4; i++)
        #pragma unroll
        for (int j = 0; j < 4; j++) {
            c[i][j][0] = 0.f; c[i][j][1] = 0.f; c[i][j][2] = 0.f; c[i][j][3] = 0.f;
        }

    const int sub = lane >> 3, r8 = lane & 7;
    const int aoff = (r8 + (sub & 1) * 8) * SSTH + (sub >> 1) * 8;
    const int boff = (r8 + (sub >> 1) * 8) * SSTH + (sub & 1) * 8;
    const uint32_t sbase = smem_u32(sh);
    const uint32_t aAddr0 = sbase + 2u * (uint32_t)(wm * SSTH + aoff);
    const uint32_t bAddr0 = sbase + 2u * (uint32_t)(ATILE + wn * SSTH + boff);

    uint4 pa[2];
    float4 rb[4];
    pa[0] = *(const uint4*)(Ag);
    pa[1] = *(const uint4*)(Ag + (size_t)64 * DM);
    #pragma unroll
    for (int i = 0; i < 4; i++) rb[i] = *(const float4*)(Wg + (size_t)i * 32 * DM);

    {
        __half* dst = sh;
        const int soA = lrA * SSTH + lvA * 8;
        *(uint4*)&dst[soA] = pa[0];
        *(uint4*)&dst[soA + 64 * SSTH] = pa[1];
        const int so = lr * SSTH + lv * 4;
        #pragma unroll
        for (int i = 0; i < 4; i++) {
            uint2 u; u.x = pack_h2(rb[i].x, rb[i].y); u.y = pack_h2(rb[i].z, rb[i].w);
            *(uint2*)&dst[ATILE + so + i * 32 * SSTH] = u;
        }
    }
    __syncthreads();

    const int NK = DM / BK;
    int stage = 0;
    for (int kt = 0; kt < NK; kt++) {
        if (kt + 1 < NK) {
            const __half* Ap = Ag + (kt + 1) * BK;
            const float*  Wp = Wg + (kt + 1) * BK;
            pa[0] = *(const uint4*)(Ap);
            pa[1] = *(const uint4*)(Ap + (size_t)64 * DM);
            #pragma unroll
            for (int i = 0; i < 4; i++) rb[i] = *(const float4*)(Wp + (size_t)i * 32 * DM);
        }

        const uint32_t stoff = (uint32_t)(stage * STG * 2);
        #pragma unroll
        for (int ks = 0; ks < 2; ks++) {
            const uint32_t kb2 = (uint32_t)(ks * 16 * 2);
            uint32_t af[4][4], bf[4][2];
            #pragma unroll
            for (int mt = 0; mt < 4; mt++)
                ldsm4(af[mt][0], af[mt][1], af[mt][2], af[mt][3],
                      aAddr0 + stoff + (uint32_t)(mt * 16 * SSTH * 2) + kb2);
            ldsm4(bf[0][0], bf[0][1], bf[1][0], bf[1][1], bAddr0 + stoff + kb2);
            ldsm4(bf[2][0], bf[2][1], bf[3][0], bf[3][1],
                  bAddr0 + stoff + (uint32_t)(16 * SSTH * 2) + kb2);
            #pragma unroll
            for (int mt = 0; mt < 4; mt++)
                #pragma unroll
                for (int nt = 0; nt < 4; nt++)
                    mma_f16(c[mt][nt], af[mt], bf[nt][0], bf[nt][1]);
        }

        if (kt + 1 < NK) {
            stage ^= 1;
            __half* dst = sh + stage * STG;
            const int soA = lrA * SSTH + lvA * 8;
            *(uint4*)&dst[soA] = pa[0];
            *(uint4*)&dst[soA + 64 * SSTH] = pa[1];
            const int so = lr * SSTH + lv * 4;
            #pragma unroll
            for (int i = 0; i < 4; i++) {
                uint2 u; u.x = pack_h2(rb[i].x, rb[i].y); u.y = pack_h2(rb[i].z, rb[i].w);
                *(uint2*)&dst[ATILE + so + i * 32 * SSTH] = u;
            }
        }
        __syncthreads();
    }

    const int rbase = blockIdx.y * BM + wm + g;
    const int cbase = blockIdx.x * BN + wn + tg * 2;
    #pragma unroll
    for (int mt = 0; mt < 4; mt++) {
        #pragma unroll
        for (int nt = 0; nt < 4; nt++) {
            const int col = cbase + nt * 8;
            const float bb0 = bias[col], bb1 = bias[col + 1];
            const int r0 = rbase + mt * 16;
            C[(size_t)r0 * DM + col]           = c[mt][nt][0] + bb0;
            C[(size_t)r0 * DM + col + 1]       = c[mt][nt][1] + bb1;
            C[(size_t)(r0 + 8) * DM + col]     = c[mt][nt][2] + bb0;
            C[(size_t)(r0 + 8) * DM + col + 1] = c[mt][nt][3] + bb1;
        }
    }
}

// ---------------- kv via mma: C[64d,64m] = K^T V over seq chunk + k_sum -----------
#define TPAD 72
__global__ void __launch_bounds__(128)
kv_mma()
{
    const int chunk = blockIdx.x;
    const int bh = blockIdx.y;
    const int b = bh >> 4, h = bh & 15;
    const int t = threadIdx.x;
    const int lane = t & 31, w = t >> 5;

    __shared__ __align__(16) __half kt[64 * TPAD];
    __shared__ __align__(16) __half vt[64 * TPAD];
    __shared__ float kssh[2][64];

    const __half* kg = g_kh + (size_t)(b * SEQ) * DM + h * DKH;
    const __half* vg = g_vh + (size_t)(b * SEQ) * DM + h * DKH;

    float c[8][4];
    #pragma unroll
    for (int i = 0; i < 8; i++) { c[i][0]=0.f; c[i][1]=0.f; c[i][2]=0.f; c[i][3]=0.f; }
    float ksl = 0.f;
    const int dks = t & 63, part = t >> 6;

    // ldsm addresses
    const int arow = (lane & 7) + ((lane >> 4) << 3);
    const int acol = w * 16 + (((lane >> 3) & 1) << 3);
    const int brow = (lane & 7) + (((lane >> 3) & 1) << 3);
    const int bcol = (lane >> 4) << 3;
    const uint32_t ktb = smem_u32(kt), vtb = smem_u32(vt);

    const int n_begin = chunk * CHSZ;
    for (int n0 = n_begin; n0 < n_begin + CHSZ; n0 += 64) {
        __syncthreads();
        #pragma unroll
        for (int j = 0; j < 4; j++) {
            const int idx = t + j * 128;
            const int row = idx >> 3, c8 = (idx & 7) * 8;
            *(uint4*)&kt[row * TPAD + c8] = *(const uint4*)&kg[(size_t)(n0 + row) * DM + c8];
            *(uint4*)&vt[row * TPAD + c8] = *(const uint4*)&vg[(size_t)(n0 + row) * DM + c8];
        }
        __syncthreads();

        // k_sum partial (fp32)
        #pragma unroll
        for (int r = 0; r < 32; r++)
            ksl += __half2float(kt[(part * 32 + r) * TPAD + dks]);

        // mma: A = K^T (trans), B = V (trans)
        #pragma unroll
        for (int kg_ = 0; kg_ < 4; kg_++) {
            uint32_t a[4];
            ldsm4t(a[0], a[1], a[2], a[3],
                   ktb + 2u * (uint32_t)((kg_ * 16 + arow) * TPAD + acol));
            #pragma unroll
            for (int mt = 0; mt < 4; mt++) {
                uint32_t b0, b1, b2, b3;
                ldsm4t(b0, b1, b2, b3,
                       vtb + 2u * (uint32_t)((kg_ * 16 + brow) * TPAD + mt * 16 + bcol));
                mma_f16(c[mt * 2],     a, b0, b1);
                mma_f16(c[mt * 2 + 1], a, b2, b3);
            }
        }
    }

    // write partials
    const int g = lane >> 2, tg = lane & 3;
    float* kvp = g_kvpart + ((size_t)chunk * 32 + bh) * (DKH * DKH);
    const int d0 = w * 16 + g, d1 = d0 + 8;
    #pragma unroll
    for (int mt = 0; mt < 4; mt++) {
        const int col0 = mt * 16 + tg * 2;
        *(float2*)&kvp[d0 * DKH + col0]     = make_float2(c[mt*2][0], c[mt*2][1]);
        *(float2*)&kvp[d1 * DKH + col0]     = make_float2(c[mt*2][2], c[mt*2][3]);
        *(float2*)&kvp[d0 * DKH + col0 + 8] = make_float2(c[mt*2+1][0], c[mt*2+1][1]);
        *(float2*)&kvp[d1 * DKH + col0 + 8] = make_float2(c[mt*2+1][2], c[mt*2+1][3]);
    }
    kssh[part][dks] = ksl;
    __syncthreads();
    if (t < 64)
        g_kspart[(chunk * 32 + bh) * DKH + t] = kssh[0][t] + kssh[1][t];
}

// ---------------- reduce partials ------------------------------------------------
__global__ void __launch_bounds__(256)
kv_reduce()
{
    const int bh = blockIdx.x;
    const int t = threadIdx.x;
    for (int e = t; e < DKH * DKH; e += 256) {
        float s = 0.f;
        #pragma unroll 8
        for (int cc = 0; cc < KVCH; cc++)
            s += g_kvpart[((size_t)cc * 32 + bh) * (DKH * DKH) + e];
        g_kv[bh * DKH * DKH + e] = s;
    }
    if (t < DKH) {
        float s = 0.f;
        #pragma unroll
        for (int cc = 0; cc < KVCH; cc++)
            s += g_kspart[(cc * 32 + bh) * DKH + t];
        g_ks[bh * DKH + t] = s;
    }
}

// ---------------- qkv via mma: out[64n,64m] = (Q' KV) / (q.ksum + eps) ------------
__global__ void __launch_bounds__(128)
qkv_mma()
{
    const int tile = blockIdx.x;
    const int bh = blockIdx.y;
    const int b = bh >> 4, h = bh & 15;
    const int t = threadIdx.x;
    const int lane = t & 31, w = t >> 5;

    __shared__ __align__(16) __half qt[64 * TPAD];
    __shared__ __align__(16) __half kvt[64 * TPAD];
    __shared__ float ksums[64], norms[64];

    const int n0 = tile * 64;
    const __half* qg = g_qh + (size_t)(b * SEQ + n0) * DM + h * DKH;

    // stage Q (fp16)
    #pragma unroll
    for (int j = 0; j < 4; j++) {
        const int idx = t + j * 128;
        const int row = idx >> 3, c8 = (idx & 7) * 8;
        *(uint4*)&qt[row * TPAD + c8] = *(const uint4*)&qg[(size_t)row * DM + c8];
    }
    // stage KV (fp32 -> fp16)
    #pragma unroll
    for (int j = 0; j < 8; j++) {
        const int idx = t + j * 128;
        const int row = idx >> 4, c4 = (idx & 15) * 4;
        const float4 f = *(const float4*)&g_kv[(size_t)bh * (DKH * DKH) + row * 64 + c4];
        *(__half2*)&kvt[row * TPAD + c4]     = __floats2half2_rn(f.x, f.y);
        *(__half2*)&kvt[row * TPAD + c4 + 2] = __floats2half2_rn(f.z, f.w);
    }
    if (t < 64) ksums[t] = g_ks[bh * DKH + t];
    __syncthreads();

    // normalizer: row = t>>1, half = t&1 over 32 d each, pair-combine via shfl
    {
        const int row = t >> 1, hf = t & 1;
        float s = 0.f;
        #pragma unroll
        for (int d = 0; d < 32; d++)
            s += __half2float(qt[row * TPAD + hf * 32 + d]) * ksums[hf * 32 + d];
        s += __shfl_xor_sync(0xFFFFFFFF, s, 1);
        if (hf == 0) norms[row] = 1.0f / (s + 1e-6f);
    }
    __syncthreads();

    float c[8][4];
    #pragma unroll
    for (int i = 0; i < 8; i++) { c[i][0]=0.f; c[i][1]=0.f; c[i][2]=0.f; c[i][3]=0.f; }

    // A = Q (non-trans), B = KV (trans)
    const int arow = w * 16 + (lane & 7) + (((lane >> 3) & 1) << 3);
    const int acol = (lane >> 4) << 3;
    const int brow = (lane & 7) + (((lane >> 3) & 1) << 3);
    const int bcol = (lane >> 4) << 3;
    const uint32_t qtb = smem_u32(qt), kvtb = smem_u32(kvt);

    #pragma unroll
    for (int kg_ = 0; kg_ < 4; kg_++) {
        uint32_t a[4];
        ldsm4(a[0], a[1], a[2], a[3],
              qtb + 2u * (uint32_t)(arow * TPAD + kg_ * 16 + acol));
        #pragma unroll
        for (int mt = 0; mt < 4; mt++) {
            uint32_t b0, b1, b2, b3;
            ldsm4t(b0, b1, b2, b3,
                   kvtb + 2u * (uint32_t)((kg_ * 16 + brow) * TPAD + mt * 16 + bcol));
            mma_f16(c[mt * 2],     a, b0, b1);
            mma_f16(c[mt * 2 + 1], a, b2, b3);
        }
    }

    // epilogue: divide + fp16 store
    const int g = lane >> 2, tg = lane & 3;
    const int r0 = w * 16 + g, r1 = r0 + 8;
    const float inv0 = norms[r0], inv1 = norms[r1];
    __half* ob0 = g_ah + (size_t)(b * SEQ + n0 + r0) * DM + h * DKH;
    __half* ob1 = g_ah + (size_t)(b * SEQ + n0 + r1) * DM + h * DKH;
    #pragma unroll
    for (int mt = 0; mt < 4; mt++) {
        const int col0 = mt * 16 + tg * 2;
        *(__half2*)&ob0[col0]     = __floats2half2_rn(c[mt*2][0] * inv0, c[mt*2][1] * inv0);
        *(__half2*)&ob1[col0]     = __floats2half2_rn(c[mt*2][2] * inv1, c[mt*2][3] * inv1);
        *(__half2*)&ob0[col0 + 8] = __floats2half2_rn(c[mt*2+1][0] * inv0, c[mt*2+1][1] * inv0);
        *(__half2*)&ob1[col0 + 8] = __floats2half2_rn(c[mt*2+1][2] * inv1, c[mt*2+1][3] * inv1);
    }
}

// ---------------- launcher -------------------------------------------------------
extern "C" void kernel_launch(void* const* d_in, const int* in_sizes, int n_in,
                              void* d_out, int out_size)
{
    const float* query = (const float*)d_in[0];
    const float* key   = (const float*)d_in[1];
    const float* value = (const float*)d_in[2];
    const float* wq = (const float*)d_in[3];
    const float* bq = (const float*)d_in[4];
    const float* wk = (const float*)d_in[5];
    const float* bk = (const float*)d_in[6];
    const float* wv = (const float*)d_in[7];
    const float* bv = (const float*)d_in[8];
    const float* wo = (const float*)d_in[9];
    const float* bo = (const float*)d_in[10];
    float* out = (float*)d_out;

    __half *qh, *kh, *vh, *ah;
    cudaGetSymbolAddress((void**)&qh, g_qh);
    cudaGetSymbolAddress((void**)&kh, g_kh);
    cudaGetSymbolAddress((void**)&vh, g_vh);
    cudaGetSymbolAddress((void**)&ah, g_ah);

    dim3 gg(DM / BN, MTOK / BM);   // (8, 128)
    gemm_p<<<gg, 256>>>(query, wq, bq, qh, 1);
    gemm_p<<<gg, 256>>>(key,   wk, bk, kh, 1);
    gemm_p<<<gg, 256>>>(value, wv, bv, vh, 0);

    kv_mma<<<dim3(KVCH, 32), 128>>>();
    kv_reduce<<<32, 256>>>();
    qkv_mma<<<dim3(SEQ / 64, 32), 128>>>();

    gemm_o<<<gg, 256>>>(ah, wo, bo, out);
}

// round 6
// speedup vs baseline: 1.1901x; 1.1901x over previous
#include <cuda_runtime.h>
#include <cuda_fp16.h>
#include <math.h>
#include <stdint.h>

#define BATCH 2
#define SEQ   8192
#define DM    1024
#define NH    16
#define DKH   64
#define MTOK  (BATCH*SEQ)
#define KVCH  32
#define CHSZ  (SEQ/KVCH)

// ---------------- scratch (static device globals; no allocations) ----------------
__device__ float g_q[(size_t)MTOK * DM];
__device__ float g_k[(size_t)MTOK * DM];
__device__ float g_v[(size_t)MTOK * DM];
__device__ float g_attn[(size_t)MTOK * DM];
__device__ float g_kvpart[KVCH * 32 * DKH * DKH];
__device__ float g_kspart[KVCH * 32 * DKH];
__device__ float g_kv[32 * DKH * DKH];
__device__ float g_ks[32 * DKH];

// ---------------- helpers ---------------------------------------------------------
__device__ __forceinline__ uint32_t smem_u32(const void* p) {
    uint32_t a;
    asm("{ .reg .u64 t; cvta.to.shared.u64 t, %1; cvt.u32.u64 %0, t; }"
        : "=r"(a) : "l"(p));
    return a;
}

__device__ __forceinline__ uint32_t pack_h2(float x, float y) {
    __half2 h = __floats2half2_rn(x, y);
    return reinterpret_cast<uint32_t&>(h);
}

__device__ __forceinline__ void ldsm4(uint32_t& r0, uint32_t& r1, uint32_t& r2,
                                      uint32_t& r3, uint32_t a) {
    asm volatile("ldmatrix.sync.aligned.m8n8.x4.shared.b16 {%0,%1,%2,%3}, [%4];"
                 : "=r"(r0), "=r"(r1), "=r"(r2), "=r"(r3) : "r"(a));
}

__device__ __forceinline__ void ldsm4t(uint32_t& r0, uint32_t& r1, uint32_t& r2,
                                       uint32_t& r3, uint32_t a) {
    asm volatile("ldmatrix.sync.aligned.m8n8.x4.trans.shared.b16 {%0,%1,%2,%3}, [%4];"
                 : "=r"(r0), "=r"(r1), "=r"(r2), "=r"(r3) : "r"(a));
}

__device__ __forceinline__ void mma_f16(float c[4], const uint32_t a[4],
                                        uint32_t b0, uint32_t b1) {
    asm volatile(
        "mma.sync.aligned.m16n8k16.row.col.f32.f16.f16.f32 "
        "{%0,%1,%2,%3},{%4,%5,%6,%7},{%8,%9},{%0,%1,%2,%3};"
        : "+f"(c[0]), "+f"(c[1]), "+f"(c[2]), "+f"(c[3])
        : "r"(a[0]), "r"(a[1]), "r"(a[2]), "r"(a[3]), "r"(b0), "r"(b1));
}

// ---------------- fp16 GEMM (round-4 proven): C = A*W^T + bias (+elu+1) -----------
#define BM 128
#define BN 128
#define BK 32
#define SSTH 40
#define ATILE (BM*SSTH)
#define STG (2*ATILE)

__global__ void __launch_bounds__(256, 1)
gemm_f16(const float* __restrict__ A, const float* __restrict__ W,
         const float* __restrict__ bias, float* __restrict__ C, int fmap)
{
    __shared__ __align__(16) __half sh[2 * STG];   // 40960 B

    const int t    = threadIdx.x;
    const int lane = t & 31, warp = t >> 5;
    const int g  = lane >> 2, tg = lane & 3;
    const int wm = (warp >> 2) * 64;
    const int wn = (warp & 3) * 32;

    const int lr = t >> 3;
    const int lv = t & 7;

    const float* Ag = A + (size_t)(blockIdx.y * BM + lr) * DM + lv * 4;
    const float* Wg = W + (size_t)(blockIdx.x * BN + lr) * DM + lv * 4;

    float c[4][4][4];
    #pragma unroll
    for (int i = 0; i < 4; i++)
        #pragma unroll
        for (int j = 0; j < 4; j++) {
            c[i][j][0] = 0.f; c[i][j][1] = 0.f; c[i][j][2] = 0.f; c[i][j][3] = 0.f;
        }

    const int sub = lane >> 3, r8 = lane & 7;
    const int aoff = (r8 + (sub & 1) * 8) * SSTH + (sub >> 1) * 8;
    const int boff = (r8 + (sub >> 1) * 8) * SSTH + (sub & 1) * 8;
    const uint32_t sbase = smem_u32(sh);
    const uint32_t aAddr0 = sbase + 2u * (uint32_t)(wm * SSTH + aoff);
    const uint32_t bAddr0 = sbase + 2u * (uint32_t)(ATILE + wn * SSTH + boff);

    float4 ra[4], rb[4];
    #pragma unroll
    for (int i = 0; i < 4; i++) ra[i] = *(const float4*)(Ag + (size_t)i * 32 * DM);
    #pragma unroll
    for (int i = 0; i < 4; i++) rb[i] = *(const float4*)(Wg + (size_t)i * 32 * DM);

    {
        __half* dst = sh;
        const int so = lr * SSTH + lv * 4;
        #pragma unroll
        for (int i = 0; i < 4; i++) {
            uint2 u; u.x = pack_h2(ra[i].x, ra[i].y); u.y = pack_h2(ra[i].z, ra[i].w);
            *(uint2*)&dst[so + i * 32 * SSTH] = u;
        }
        #pragma unroll
        for (int i = 0; i < 4; i++) {
            uint2 u; u.x = pack_h2(rb[i].x, rb[i].y); u.y = pack_h2(rb[i].z, rb[i].w);
            *(uint2*)&dst[ATILE + so + i * 32 * SSTH] = u;
        }
    }
    __syncthreads();

    const int NK = DM / BK;
    int stage = 0;
    for (int kt = 0; kt < NK; kt++) {
        if (kt + 1 < NK) {
            const float* Ap = Ag + (kt + 1) * BK;
            const float* Wp = Wg + (kt + 1) * BK;
            #pragma unroll
            for (int i = 0; i < 4; i++) ra[i] = *(const float4*)(Ap + (size_t)i * 32 * DM);
            #pragma unroll
            for (int i = 0; i < 4; i++) rb[i] = *(const float4*)(Wp + (size_t)i * 32 * DM);
        }

        const uint32_t stoff = (uint32_t)(stage * STG * 2);
        #pragma unroll
        for (int ks = 0; ks < 2; ks++) {
            const uint32_t kb2 = (uint32_t)(ks * 16 * 2);
            uint32_t af[4][4], bf[4][2];
            #pragma unroll
            for (int mt = 0; mt < 4; mt++)
                ldsm4(af[mt][0], af[mt][1], af[mt][2], af[mt][3],
                      aAddr0 + stoff + (uint32_t)(mt * 16 * SSTH * 2) + kb2);
            ldsm4(bf[0][0], bf[0][1], bf[1][0], bf[1][1], bAddr0 + stoff + kb2);
            ldsm4(bf[2][0], bf[2][1], bf[3][0], bf[3][1],
                  bAddr0 + stoff + (uint32_t)(16 * SSTH * 2) + kb2);
            #pragma unroll
            for (int mt = 0; mt < 4; mt++)
                #pragma unroll
                for (int nt = 0; nt < 4; nt++)
                    mma_f16(c[mt][nt], af[mt], bf[nt][0], bf[nt][1]);
        }

        if (kt + 1 < NK) {
            stage ^= 1;
            __half* dst = sh + stage * STG;
            const int so = lr * SSTH + lv * 4;
            #pragma unroll
            for (int i = 0; i < 4; i++) {
                uint2 u; u.x = pack_h2(ra[i].x, ra[i].y); u.y = pack_h2(ra[i].z, ra[i].w);
                *(uint2*)&dst[so + i * 32 * SSTH] = u;
            }
            #pragma unroll
            for (int i = 0; i < 4; i++) {
                uint2 u; u.x = pack_h2(rb[i].x, rb[i].y); u.y = pack_h2(rb[i].z, rb[i].w);
                *(uint2*)&dst[ATILE + so + i * 32 * SSTH] = u;
            }
        }
        __syncthreads();
    }

    const int rbase = blockIdx.y * BM + wm + g;
    const int cbase = blockIdx.x * BN + wn + tg * 2;
    #pragma unroll
    for (int mt = 0; mt < 4; mt++) {
        #pragma unroll
        for (int nt = 0; nt < 4; nt++) {
            const int col = cbase + nt * 8;
            const float bb0 = bias[col], bb1 = bias[col + 1];
            const int r0 = rbase + mt * 16;
            float v00 = c[mt][nt][0] + bb0;
            float v01 = c[mt][nt][1] + bb1;
            float v10 = c[mt][nt][2] + bb0;
            float v11 = c[mt][nt][3] + bb1;
            if (fmap) {   // elu(x)+1
                v00 = v00 > 0.f ? v00 + 1.f : __expf(v00);
                v01 = v01 > 0.f ? v01 + 1.f : __expf(v01);
                v10 = v10 > 0.f ? v10 + 1.f : __expf(v10);
                v11 = v11 > 0.f ? v11 + 1.f : __expf(v11);
            }
            C[(size_t)r0 * DM + col]           = v00;
            C[(size_t)r0 * DM + col + 1]       = v01;
            C[(size_t)(r0 + 8) * DM + col]     = v10;
            C[(size_t)(r0 + 8) * DM + col + 1] = v11;
        }
    }
}

// ---------------- kv via mma (fp32 in): C[64d,64m] = K^T V + k_sum ----------------
#define TPAD 72
__global__ void __launch_bounds__(128)
kv_mma()
{
    const int chunk = blockIdx.x;
    const int bh = blockIdx.y;
    const int b = bh >> 4, h = bh & 15;
    const int t = threadIdx.x;
    const int lane = t & 31, w = t >> 5;

    __shared__ __align__(16) __half kt[64 * TPAD];
    __shared__ __align__(16) __half vt[64 * TPAD];
    __shared__ float kss[8][64];

    const float* kg = g_k + (size_t)(b * SEQ) * DM + h * DKH;
    const float* vg = g_v + (size_t)(b * SEQ) * DM + h * DKH;

    float c[8][4];
    #pragma unroll
    for (int i = 0; i < 8; i++) { c[i][0]=0.f; c[i][1]=0.f; c[i][2]=0.f; c[i][3]=0.f; }
    float4 ks4 = make_float4(0.f, 0.f, 0.f, 0.f);

    // staging map: idx = t + 128j -> row = t>>4 + 8j, cols (t&15)*4 .. +3 (fixed)
    const int cc = (t & 15) * 4;

    // ldsm addresses
    const int arow = (lane & 7) + ((lane >> 4) << 3);
    const int acol = w * 16 + (((lane >> 3) & 1) << 3);
    const int brow = (lane & 7) + (((lane >> 3) & 1) << 3);
    const int bcol = (lane >> 4) << 3;
    const uint32_t ktb = smem_u32(kt), vtb = smem_u32(vt);

    const int n_begin = chunk * CHSZ;
    for (int n0 = n_begin; n0 < n_begin + CHSZ; n0 += 64) {
        __syncthreads();
        #pragma unroll
        for (int j = 0; j < 8; j++) {
            const int row = (t >> 4) + 8 * j;
            const float4 fk = *(const float4*)&kg[(size_t)(n0 + row) * DM + cc];
            const float4 fv = *(const float4*)&vg[(size_t)(n0 + row) * DM + cc];
            __half2* kd = (__half2*)&kt[row * TPAD + cc];
            __half2* vd = (__half2*)&vt[row * TPAD + cc];
            kd[0] = __floats2half2_rn(fk.x, fk.y);
            kd[1] = __floats2half2_rn(fk.z, fk.w);
            vd[0] = __floats2half2_rn(fv.x, fv.y);
            vd[1] = __floats2half2_rn(fv.z, fv.w);
            ks4.x += fk.x; ks4.y += fk.y; ks4.z += fk.z; ks4.w += fk.w;
        }
        __syncthreads();

        // mma: A = K^T (trans), B = V (trans)
        #pragma unroll
        for (int kg_ = 0; kg_ < 4; kg_++) {
            uint32_t a[4];
            ldsm4t(a[0], a[1], a[2], a[3],
                   ktb + 2u * (uint32_t)((kg_ * 16 + arow) * TPAD + acol));
            #pragma unroll
            for (int mt = 0; mt < 4; mt++) {
                uint32_t b0, b1, b2, b3;
                ldsm4t(b0, b1, b2, b3,
                       vtb + 2u * (uint32_t)((kg_ * 16 + brow) * TPAD + mt * 16 + bcol));
                mma_f16(c[mt * 2],     a, b0, b1);
                mma_f16(c[mt * 2 + 1], a, b2, b3);
            }
        }
    }

    // write partials
    const int g = lane >> 2, tg = lane & 3;
    float* kvp = g_kvpart + ((size_t)chunk * 32 + bh) * (DKH * DKH);
    const int d0 = w * 16 + g, d1 = d0 + 8;
    #pragma unroll
    for (int mt = 0; mt < 4; mt++) {
        const int col0 = mt * 16 + tg * 2;
        *(float2*)&kvp[d0 * DKH + col0]     = make_float2(c[mt*2][0], c[mt*2][1]);
        *(float2*)&kvp[d1 * DKH + col0]     = make_float2(c[mt*2][2], c[mt*2][3]);
        *(float2*)&kvp[d0 * DKH + col0 + 8] = make_float2(c[mt*2+1][0], c[mt*2+1][1]);
        *(float2*)&kvp[d1 * DKH + col0 + 8] = make_float2(c[mt*2+1][2], c[mt*2+1][3]);
    }
    // k_sum: thread owns cols cc..cc+3, partial over its 8-row stripes
    kss[t >> 4][cc]     = ks4.x;
    kss[t >> 4][cc + 1] = ks4.y;
    kss[t >> 4][cc + 2] = ks4.z;
    kss[t >> 4][cc + 3] = ks4.w;
    __syncthreads();
    if (t < 64) {
        float s = 0.f;
        #pragma unroll
        for (int p = 0; p < 8; p++) s += kss[p][t];
        g_kspart[(chunk * 32 + bh) * DKH + t] = s;
    }
}

// ---------------- reduce partials ------------------------------------------------
__global__ void __launch_bounds__(256)
kv_reduce()
{
    const int bh = blockIdx.x;
    const int t = threadIdx.x;
    for (int e = t; e < DKH * DKH; e += 256) {
        float s = 0.f;
        #pragma unroll 8
        for (int cc = 0; cc < KVCH; cc++)
            s += g_kvpart[((size_t)cc * 32 + bh) * (DKH * DKH) + e];
        g_kv[bh * DKH * DKH + e] = s;
    }
    if (t < DKH) {
        float s = 0.f;
        #pragma unroll
        for (int cc = 0; cc < KVCH; cc++)
            s += g_kspart[(cc * 32 + bh) * DKH + t];
        g_ks[bh * DKH + t] = s;
    }
}

// ---------------- qkv via mma (fp32 in/out): out = (Q' KV) / (q.ksum + eps) -------
__global__ void __launch_bounds__(128)
qkv_mma()
{
    const int tile = blockIdx.x;
    const int bh = blockIdx.y;
    const int b = bh >> 4, h = bh & 15;
    const int t = threadIdx.x;
    const int lane = t & 31, w = t >> 5;

    __shared__ __align__(16) __half qt[64 * TPAD];
    __shared__ __align__(16) __half kvt[64 * TPAD];
    __shared__ float ksums[64], norms[64];

    const int n0 = tile * 64;
    const float* qg = g_q + (size_t)(b * SEQ + n0) * DM + h * DKH;

    // stage Q (fp32 -> fp16)
    const int cc = (t & 15) * 4;
    #pragma unroll
    for (int j = 0; j < 8; j++) {
        const int row = (t >> 4) + 8 * j;
        const float4 f = *(const float4*)&qg[(size_t)row * DM + cc];
        __half2* qd = (__half2*)&qt[row * TPAD + cc];
        qd[0] = __floats2half2_rn(f.x, f.y);
        qd[1] = __floats2half2_rn(f.z, f.w);
    }
    // stage KV (fp32 -> fp16)
    #pragma unroll
    for (int j = 0; j < 8; j++) {
        const int idx = t + j * 128;
        const int row = idx >> 4, c4 = (idx & 15) * 4;
        const float4 f = *(const float4*)&g_kv[(size_t)bh * (DKH * DKH) + row * 64 + c4];
        *(__half2*)&kvt[row * TPAD + c4]     = __floats2half2_rn(f.x, f.y);
        *(__half2*)&kvt[row * TPAD + c4 + 2] = __floats2half2_rn(f.z, f.w);
    }
    if (t < 64) ksums[t] = g_ks[bh * DKH + t];
    __syncthreads();

    // normalizer
    {
        const int row = t >> 1, hf = t & 1;
        float s = 0.f;
        #pragma unroll
        for (int d = 0; d < 32; d++)
            s += __half2float(qt[row * TPAD + hf * 32 + d]) * ksums[hf * 32 + d];
        s += __shfl_xor_sync(0xFFFFFFFF, s, 1);
        if (hf == 0) norms[row] = 1.0f / (s + 1e-6f);
    }
    __syncthreads();

    float c[8][4];
    #pragma unroll
    for (int i = 0; i < 8; i++) { c[i][0]=0.f; c[i][1]=0.f; c[i][2]=0.f; c[i][3]=0.f; }

    // A = Q (non-trans), B = KV (trans)
    const int arow = w * 16 + (lane & 7) + (((lane >> 3) & 1) << 3);
    const int acol = (lane >> 4) << 3;
    const int brow = (lane & 7) + (((lane >> 3) & 1) << 3);
    const int bcol = (lane >> 4) << 3;
    const uint32_t qtb = smem_u32(qt), kvtb = smem_u32(kvt);

    #pragma unroll
    for (int kg_ = 0; kg_ < 4; kg_++) {
        uint32_t a[4];
        ldsm4(a[0], a[1], a[2], a[3],
              qtb + 2u * (uint32_t)(arow * TPAD + kg_ * 16 + acol));
        #pragma unroll
        for (int mt = 0; mt < 4; mt++) {
            uint32_t b0, b1, b2, b3;
            ldsm4t(b0, b1, b2, b3,
                   kvtb + 2u * (uint32_t)((kg_ * 16 + brow) * TPAD + mt * 16 + bcol));
            mma_f16(c[mt * 2],     a, b0, b1);
            mma_f16(c[mt * 2 + 1], a, b2, b3);
        }
    }

    // epilogue: divide + fp32 store
    const int g = lane >> 2, tg = lane & 3;
    const int r0 = w * 16 + g, r1 = r0 + 8;
    const float inv0 = norms[r0], inv1 = norms[r1];
    float* ob0 = g_attn + (size_t)(b * SEQ + n0 + r0) * DM + h * DKH;
    float* ob1 = g_attn + (size_t)(b * SEQ + n0 + r1) * DM + h * DKH;
    #pragma unroll
    for (int mt = 0; mt < 4; mt++) {
        const int col0 = mt * 16 + tg * 2;
        *(float2*)&ob0[col0]     = make_float2(c[mt*2][0] * inv0, c[mt*2][1] * inv0);
        *(float2*)&ob1[col0]     = make_float2(c[mt*2][2] * inv1, c[mt*2][3] * inv1);
        *(float2*)&ob0[col0 + 8] = make_float2(c[mt*2+1][0] * inv0, c[mt*2+1][1] * inv0);
        *(float2*)&ob1[col0 + 8] = make_float2(c[mt*2+1][2] * inv1, c[mt*2+1][3] * inv1);
    }
}

// ---------------- launcher -------------------------------------------------------
extern "C" void kernel_launch(void* const* d_in, const int* in_sizes, int n_in,
                              void* d_out, int out_size)
{
    const float* query = (const float*)d_in[0];
    const float* key   = (const float*)d_in[1];
    const float* value = (const float*)d_in[2];
    const float* wq = (const float*)d_in[3];
    const float* bq = (const float*)d_in[4];
    const float* wk = (const float*)d_in[5];
    const float* bk = (const float*)d_in[6];
    const float* wv = (const float*)d_in[7];
    const float* bv = (const float*)d_in[8];
    const float* wo = (const float*)d_in[9];
    const float* bo = (const float*)d_in[10];
    float* out = (float*)d_out;

    float *qb, *kb, *vb, *attn;
    cudaGetSymbolAddress((void**)&qb,   g_q);
    cudaGetSymbolAddress((void**)&kb,   g_k);
    cudaGetSymbolAddress((void**)&vb,   g_v);
    cudaGetSymbolAddress((void**)&attn, g_attn);

    dim3 gg(DM / BN, MTOK / BM);   // (8, 128)
    gemm_f16<<<gg, 256>>>(query, wq, bq, qb, 1);
    gemm_f16<<<gg, 256>>>(key,   wk, bk, kb, 1);
    gemm_f16<<<gg, 256>>>(value, wv, bv, vb, 0);

    kv_mma<<<dim3(KVCH, 32), 128>>>();
    kv_reduce<<<32, 256>>>();
    qkv_mma<<<dim3(SEQ / 64, 32), 128>>>();

    gemm_f16<<<gg, 256>>>(attn, wo, bo, out, 0);
}

// round 7
// speedup vs baseline: 1.2778x; 1.0737x over previous
#include <cuda_runtime.h>
#include <cuda_fp16.h>
#include <math.h>
#include <stdint.h>

#define BATCH 2
#define SEQ   8192
#define DM    1024
#define NH    16
#define DKH   64
#define MTOK  (BATCH*SEQ)
#define KVCH  32
#define CHSZ  (SEQ/KVCH)

// ---------------- scratch (static device globals; no allocations) ----------------
__device__ float g_q[(size_t)MTOK * DM];
__device__ float g_k[(size_t)MTOK * DM];
__device__ float g_v[(size_t)MTOK * DM];
__device__ float g_attn[(size_t)MTOK * DM];
__device__ float g_kvpart[KVCH * 32 * DKH * DKH];
__device__ float g_kspart[KVCH * 32 * DKH];
__device__ float g_kv[32 * DKH * DKH];
__device__ float g_ks[32 * DKH];

// ---------------- helpers ---------------------------------------------------------
__device__ __forceinline__ uint32_t smem_u32(const void* p) {
    uint32_t a;
    asm("{ .reg .u64 t; cvta.to.shared.u64 t, %1; cvt.u32.u64 %0, t; }"
        : "=r"(a) : "l"(p));
    return a;
}

__device__ __forceinline__ uint32_t pack_h2(float x, float y) {
    __half2 h = __floats2half2_rn(x, y);
    return reinterpret_cast<uint32_t&>(h);
}

__device__ __forceinline__ void ldsm4(uint32_t& r0, uint32_t& r1, uint32_t& r2,
                                      uint32_t& r3, uint32_t a) {
    asm volatile("ldmatrix.sync.aligned.m8n8.x4.shared.b16 {%0,%1,%2,%3}, [%4];"
                 : "=r"(r0), "=r"(r1), "=r"(r2), "=r"(r3) : "r"(a));
}

__device__ __forceinline__ void ldsm4t(uint32_t& r0, uint32_t& r1, uint32_t& r2,
                                       uint32_t& r3, uint32_t a) {
    asm volatile("ldmatrix.sync.aligned.m8n8.x4.trans.shared.b16 {%0,%1,%2,%3}, [%4];"
                 : "=r"(r0), "=r"(r1), "=r"(r2), "=r"(r3) : "r"(a));
}

__device__ __forceinline__ void mma_f16(float c[4], const uint32_t a[4],
                                        uint32_t b0, uint32_t b1) {
    asm volatile(
        "mma.sync.aligned.m16n8k16.row.col.f32.f16.f16.f32 "
        "{%0,%1,%2,%3},{%4,%5,%6,%7},{%8,%9},{%0,%1,%2,%3};"
        : "+f"(c[0]), "+f"(c[1]), "+f"(c[2]), "+f"(c[3])
        : "r"(a[0]), "r"(a[1]), "r"(a[2]), "r"(a[3]), "r"(b0), "r"(b1));
}

// ---------------- fp16 GEMM body: C = A*W^T + bias (+elu+1) -----------------------
#define BM 128
#define BN 128
#define BK 32
#define SSTH 40
#define ATILE (BM*SSTH)
#define STG (2*ATILE)

__device__ __forceinline__ void
gemm_body(const float* __restrict__ A, const float* __restrict__ W,
          const float* __restrict__ bias, float* __restrict__ C, int fmap)
{
    __shared__ __align__(16) __half sh[2 * STG];   // 40960 B

    const int t    = threadIdx.x;
    const int lane = t & 31, warp = t >> 5;
    const int g  = lane >> 2, tg = lane & 3;
    const int wm = (warp >> 2) * 64;
    const int wn = (warp & 3) * 32;

    const int lr = t >> 3;
    const int lv = t & 7;

    const float* Ag = A + (size_t)(blockIdx.y * BM + lr) * DM + lv * 4;
    const float* Wg = W + (size_t)(blockIdx.x * BN + lr) * DM + lv * 4;

    float c[4][4][4];
    #pragma unroll
    for (int i = 0; i < 4; i++)
        #pragma unroll
        for (int j = 0; j < 4; j++) {
            c[i][j][0] = 0.f; c[i][j][1] = 0.f; c[i][j][2] = 0.f; c[i][j][3] = 0.f;
        }

    const int sub = lane >> 3, r8 = lane & 7;
    const int aoff = (r8 + (sub & 1) * 8) * SSTH + (sub >> 1) * 8;
    const int boff = (r8 + (sub >> 1) * 8) * SSTH + (sub & 1) * 8;
    const uint32_t sbase = smem_u32(sh);
    const uint32_t aAddr0 = sbase + 2u * (uint32_t)(wm * SSTH + aoff);
    const uint32_t bAddr0 = sbase + 2u * (uint32_t)(ATILE + wn * SSTH + boff);

    float4 ra[4], rb[4];
    #pragma unroll
    for (int i = 0; i < 4; i++) ra[i] = *(const float4*)(Ag + (size_t)i * 32 * DM);
    #pragma unroll
    for (int i = 0; i < 4; i++) rb[i] = *(const float4*)(Wg + (size_t)i * 32 * DM);

    {
        __half* dst = sh;
        const int so = lr * SSTH + lv * 4;
        #pragma unroll
        for (int i = 0; i < 4; i++) {
            uint2 u; u.x = pack_h2(ra[i].x, ra[i].y); u.y = pack_h2(ra[i].z, ra[i].w);
            *(uint2*)&dst[so + i * 32 * SSTH] = u;
        }
        #pragma unroll
        for (int i = 0; i < 4; i++) {
            uint2 u; u.x = pack_h2(rb[i].x, rb[i].y); u.y = pack_h2(rb[i].z, rb[i].w);
            *(uint2*)&dst[ATILE + so + i * 32 * SSTH] = u;
        }
    }
    __syncthreads();

    const int NK = DM / BK;
    int stage = 0;
    for (int kt = 0; kt < NK; kt++) {
        if (kt + 1 < NK) {
            const float* Ap = Ag + (kt + 1) * BK;
            const float* Wp = Wg + (kt + 1) * BK;
            #pragma unroll
            for (int i = 0; i < 4; i++) ra[i] = *(const float4*)(Ap + (size_t)i * 32 * DM);
            #pragma unroll
            for (int i = 0; i < 4; i++) rb[i] = *(const float4*)(Wp + (size_t)i * 32 * DM);
        }

        const uint32_t stoff = (uint32_t)(stage * STG * 2);
        #pragma unroll
        for (int ks = 0; ks < 2; ks++) {
            const uint32_t kb2 = (uint32_t)(ks * 16 * 2);
            uint32_t af[4][4], bf[4][2];
            #pragma unroll
            for (int mt = 0; mt < 4; mt++)
                ldsm4(af[mt][0], af[mt][1], af[mt][2], af[mt][3],
                      aAddr0 + stoff + (uint32_t)(mt * 16 * SSTH * 2) + kb2);
            ldsm4(bf[0][0], bf[0][1], bf[1][0], bf[1][1], bAddr0 + stoff + kb2);
            ldsm4(bf[2][0], bf[2][1], bf[3][0], bf[3][1],
                  bAddr0 + stoff + (uint32_t)(16 * SSTH * 2) + kb2);
            #pragma unroll
            for (int mt = 0; mt < 4; mt++)
                #pragma unroll
                for (int nt = 0; nt < 4; nt++)
                    mma_f16(c[mt][nt], af[mt], bf[nt][0], bf[nt][1]);
        }

        if (kt + 1 < NK) {
            stage ^= 1;
            __half* dst = sh + stage * STG;
            const int so = lr * SSTH + lv * 4;
            #pragma unroll
            for (int i = 0; i < 4; i++) {
                uint2 u; u.x = pack_h2(ra[i].x, ra[i].y); u.y = pack_h2(ra[i].z, ra[i].w);
                *(uint2*)&dst[so + i * 32 * SSTH] = u;
            }
            #pragma unroll
            for (int i = 0; i < 4; i++) {
                uint2 u; u.x = pack_h2(rb[i].x, rb[i].y); u.y = pack_h2(rb[i].z, rb[i].w);
                *(uint2*)&dst[ATILE + so + i * 32 * SSTH] = u;
            }
        }
        __syncthreads();
    }

    const int rbase = blockIdx.y * BM + wm + g;
    const int cbase = blockIdx.x * BN + wn + tg * 2;
    #pragma unroll
    for (int mt = 0; mt < 4; mt++) {
        #pragma unroll
        for (int nt = 0; nt < 4; nt++) {
            const int col = cbase + nt * 8;
            const float bb0 = bias[col], bb1 = bias[col + 1];
            const int r0 = rbase + mt * 16;
            float v00 = c[mt][nt][0] + bb0;
            float v01 = c[mt][nt][1] + bb1;
            float v10 = c[mt][nt][2] + bb0;
            float v11 = c[mt][nt][3] + bb1;
            if (fmap) {   // elu(x)+1
                v00 = v00 > 0.f ? v00 + 1.f : __expf(v00);
                v01 = v01 > 0.f ? v01 + 1.f : __expf(v01);
                v10 = v10 > 0.f ? v10 + 1.f : __expf(v10);
                v11 = v11 > 0.f ? v11 + 1.f : __expf(v11);
            }
            C[(size_t)r0 * DM + col]           = v00;
            C[(size_t)r0 * DM + col + 1]       = v01;
            C[(size_t)(r0 + 8) * DM + col]     = v10;
            C[(size_t)(r0 + 8) * DM + col + 1] = v11;
        }
    }
}

// merged projection GEMM: z=0 -> Q (fmap), z=1 -> K (fmap), z=2 -> V
__global__ void __launch_bounds__(256, 1)
gemm_qkv(const float* __restrict__ q, const float* __restrict__ k,
         const float* __restrict__ v,
         const float* __restrict__ wq, const float* __restrict__ bq,
         const float* __restrict__ wk, const float* __restrict__ bk,
         const float* __restrict__ wv, const float* __restrict__ bv,
         float* __restrict__ oq, float* __restrict__ ok, float* __restrict__ ov)
{
    const int z = blockIdx.z;
    const float* A = (z == 0) ? q : (z == 1) ? k : v;
    const float* W = (z == 0) ? wq : (z == 1) ? wk : wv;
    const float* B = (z == 0) ? bq : (z == 1) ? bk : bv;
    float*       C = (z == 0) ? oq : (z == 1) ? ok : ov;
    gemm_body(A, W, B, C, z == 2 ? 0 : 1);
}

__global__ void __launch_bounds__(256, 1)
gemm_f16(const float* __restrict__ A, const float* __restrict__ W,
         const float* __restrict__ bias, float* __restrict__ C, int fmap)
{
    gemm_body(A, W, bias, C, fmap);
}

// ---------------- kv via mma (fp32 in): C[64d,64m] = K^T V + k_sum ----------------
#define TPAD 72
__global__ void __launch_bounds__(128)
kv_mma()
{
    const int chunk = blockIdx.x;
    const int bh = blockIdx.y;
    const int b = bh >> 4, h = bh & 15;
    const int t = threadIdx.x;
    const int lane = t & 31, w = t >> 5;

    __shared__ __align__(16) __half kt[64 * TPAD];
    __shared__ __align__(16) __half vt[64 * TPAD];
    __shared__ float kss[8][64];

    const float* kg = g_k + (size_t)(b * SEQ) * DM + h * DKH;
    const float* vg = g_v + (size_t)(b * SEQ) * DM + h * DKH;

    float c[8][4];
    #pragma unroll
    for (int i = 0; i < 8; i++) { c[i][0]=0.f; c[i][1]=0.f; c[i][2]=0.f; c[i][3]=0.f; }
    float4 ks4 = make_float4(0.f, 0.f, 0.f, 0.f);

    const int cc = (t & 15) * 4;

    const int arow = (lane & 7) + ((lane >> 4) << 3);
    const int acol = w * 16 + (((lane >> 3) & 1) << 3);
    const int brow = (lane & 7) + (((lane >> 3) & 1) << 3);
    const int bcol = (lane >> 4) << 3;
    const uint32_t ktb = smem_u32(kt), vtb = smem_u32(vt);

    const int n_begin = chunk * CHSZ;
    for (int n0 = n_begin; n0 < n_begin + CHSZ; n0 += 64) {
        __syncthreads();
        #pragma unroll
        for (int j = 0; j < 8; j++) {
            const int row = (t >> 4) + 8 * j;
            const float4 fk = *(const float4*)&kg[(size_t)(n0 + row) * DM + cc];
            const float4 fv = *(const float4*)&vg[(size_t)(n0 + row) * DM + cc];
            __half2* kd = (__half2*)&kt[row * TPAD + cc];
            __half2* vd = (__half2*)&vt[row * TPAD + cc];
            kd[0] = __floats2half2_rn(fk.x, fk.y);
            kd[1] = __floats2half2_rn(fk.z, fk.w);
            vd[0] = __floats2half2_rn(fv.x, fv.y);
            vd[1] = __floats2half2_rn(fv.z, fv.w);
            ks4.x += fk.x; ks4.y += fk.y; ks4.z += fk.z; ks4.w += fk.w;
        }
        __syncthreads();

        #pragma unroll
        for (int kg_ = 0; kg_ < 4; kg_++) {
            uint32_t a[4];
            ldsm4t(a[0], a[1], a[2], a[3],
                   ktb + 2u * (uint32_t)((kg_ * 16 + arow) * TPAD + acol));
            #pragma unroll
            for (int mt = 0; mt < 4; mt++) {
                uint32_t b0, b1, b2, b3;
                ldsm4t(b0, b1, b2, b3,
                       vtb + 2u * (uint32_t)((kg_ * 16 + brow) * TPAD + mt * 16 + bcol));
                mma_f16(c[mt * 2],     a, b0, b1);
                mma_f16(c[mt * 2 + 1], a, b2, b3);
            }
        }
    }

    const int g = lane >> 2, tg = lane & 3;
    float* kvp = g_kvpart + ((size_t)chunk * 32 + bh) * (DKH * DKH);
    const int d0 = w * 16 + g, d1 = d0 + 8;
    #pragma unroll
    for (int mt = 0; mt < 4; mt++) {
        const int col0 = mt * 16 + tg * 2;
        *(float2*)&kvp[d0 * DKH + col0]     = make_float2(c[mt*2][0], c[mt*2][1]);
        *(float2*)&kvp[d1 * DKH + col0]     = make_float2(c[mt*2][2], c[mt*2][3]);
        *(float2*)&kvp[d0 * DKH + col0 + 8] = make_float2(c[mt*2+1][0], c[mt*2+1][1]);
        *(float2*)&kvp[d1 * DKH + col0 + 8] = make_float2(c[mt*2+1][2], c[mt*2+1][3]);
    }
    kss[t >> 4][cc]     = ks4.x;
    kss[t >> 4][cc + 1] = ks4.y;
    kss[t >> 4][cc + 2] = ks4.z;
    kss[t >> 4][cc + 3] = ks4.w;
    __syncthreads();
    if (t < 64) {
        float s = 0.f;
        #pragma unroll
        for (int p = 0; p < 8; p++) s += kss[p][t];
        g_kspart[(chunk * 32 + bh) * DKH + t] = s;
    }
}

// ---------------- reduce partials (parallel slices) -------------------------------
__global__ void __launch_bounds__(256)
kv_reduce()
{
    const int bh = blockIdx.x;
    const int s = blockIdx.y;         // 8 slices of 512 elements
    const int t = threadIdx.x;
    const int e = s * 512 + t * 2;
    float2 acc = make_float2(0.f, 0.f);
    #pragma unroll 8
    for (int cc = 0; cc < KVCH; cc++) {
        const float2 p = *(const float2*)&g_kvpart[((size_t)cc * 32 + bh) * (DKH * DKH) + e];
        acc.x += p.x; acc.y += p.y;
    }
    *(float2*)&g_kv[bh * DKH * DKH + e] = acc;

    if (s == 0 && t < DKH) {
        float sum = 0.f;
        #pragma unroll
        for (int cc = 0; cc < KVCH; cc++)
            sum += g_kspart[(cc * 32 + bh) * DKH + t];
        g_ks[bh * DKH + t] = sum;
    }
}

// ---------------- qkv via mma v2: 128 rows/block, 256 threads ---------------------
#define QROWS 128
__global__ void __launch_bounds__(256)
qkv_mma()
{
    const int tile = blockIdx.x;
    const int bh = blockIdx.y;
    const int b = bh >> 4, h = bh & 15;
    const int t = threadIdx.x;
    const int lane = t & 31, w = t >> 5;    // 8 warps

    __shared__ __align__(16) __half qt[QROWS * TPAD];   // 18432 B
    __shared__ __align__(16) __half kvt[64 * TPAD];     //  9216 B
    __shared__ float ksums[64], norms[QROWS];

    const int n0 = tile * QROWS;
    const float* qg = g_q + (size_t)(b * SEQ + n0) * DM + h * DKH;

    // stage Q (fp32 -> fp16): 2048 float4s
    #pragma unroll
    for (int j = 0; j < 8; j++) {
        const int idx = t + j * 256;
        const int row = idx >> 4, c4 = (idx & 15) * 4;
        const float4 f = *(const float4*)&qg[(size_t)row * DM + c4];
        __half2* qd = (__half2*)&qt[row * TPAD + c4];
        qd[0] = __floats2half2_rn(f.x, f.y);
        qd[1] = __floats2half2_rn(f.z, f.w);
    }
    // stage KV (fp32 -> fp16): 1024 float4s
    #pragma unroll
    for (int j = 0; j < 4; j++) {
        const int idx = t + j * 256;
        const int row = idx >> 4, c4 = (idx & 15) * 4;
        const float4 f = *(const float4*)&g_kv[(size_t)bh * (DKH * DKH) + row * 64 + c4];
        *(__half2*)&kvt[row * TPAD + c4]     = __floats2half2_rn(f.x, f.y);
        *(__half2*)&kvt[row * TPAD + c4 + 2] = __floats2half2_rn(f.z, f.w);
    }
    if (t < 64) ksums[t] = g_ks[bh * DKH + t];
    __syncthreads();

    // normalizer: 256 threads cover 128 rows (2 threads/row, 32 d each)
    {
        const int row = t >> 1, hf = t & 1;
        float s = 0.f;
        #pragma unroll
        for (int d = 0; d < 32; d++)
            s += __half2float(qt[row * TPAD + hf * 32 + d]) * ksums[hf * 32 + d];
        s += __shfl_xor_sync(0xFFFFFFFF, s, 1);
        if (hf == 0) norms[row] = 1.0f / (s + 1e-6f);
    }
    __syncthreads();

    float c[8][4];
    #pragma unroll
    for (int i = 0; i < 8; i++) { c[i][0]=0.f; c[i][1]=0.f; c[i][2]=0.f; c[i][3]=0.f; }

    // warp w handles rows w*16..w*16+15; A = Q (non-trans), B = KV (trans)
    const int arow = w * 16 + (lane & 7) + (((lane >> 3) & 1) << 3);
    const int acol = (lane >> 4) << 3;
    const int brow = (lane & 7) + (((lane >> 3) & 1) << 3);
    const int bcol = (lane >> 4) << 3;
    const uint32_t qtb = smem_u32(qt), kvtb = smem_u32(kvt);

    #pragma unroll
    for (int kg_ = 0; kg_ < 4; kg_++) {
        uint32_t a[4];
        ldsm4(a[0], a[1], a[2], a[3],
              qtb + 2u * (uint32_t)(arow * TPAD + kg_ * 16 + acol));
        #pragma unroll
        for (int mt = 0; mt < 4; mt++) {
            uint32_t b0, b1, b2, b3;
            ldsm4t(b0, b1, b2, b3,
                   kvtb + 2u * (uint32_t)((kg_ * 16 + brow) * TPAD + mt * 16 + bcol));
            mma_f16(c[mt * 2],     a, b0, b1);
            mma_f16(c[mt * 2 + 1], a, b2, b3);
        }
    }

    // epilogue: divide + fp32 store
    const int g = lane >> 2, tg = lane & 3;
    const int r0 = w * 16 + g, r1 = r0 + 8;
    const float inv0 = norms[r0], inv1 = norms[r1];
    float* ob0 = g_attn + (size_t)(b * SEQ + n0 + r0) * DM + h * DKH;
    float* ob1 = g_attn + (size_t)(b * SEQ + n0 + r1) * DM + h * DKH;
    #pragma unroll
    for (int mt = 0; mt < 4; mt++) {
        const int col0 = mt * 16 + tg * 2;
        *(float2*)&ob0[col0]     = make_float2(c[mt*2][0] * inv0, c[mt*2][1] * inv0);
        *(float2*)&ob1[col0]     = make_float2(c[mt*2][2] * inv1, c[mt*2][3] * inv1);
        *(float2*)&ob0[col0 + 8] = make_float2(c[mt*2+1][0] * inv0, c[mt*2+1][1] * inv0);
        *(float2*)&ob1[col0 + 8] = make_float2(c[mt*2+1][2] * inv1, c[mt*2+1][3] * inv1);
    }
}

// ---------------- launcher -------------------------------------------------------
extern "C" void kernel_launch(void* const* d_in, const int* in_sizes, int n_in,
                              void* d_out, int out_size)
{
    const float* query = (const float*)d_in[0];
    const float* key   = (const float*)d_in[1];
    const float* value = (const float*)d_in[2];
    const float* wq = (const float*)d_in[3];
    const float* bq = (const float*)d_in[4];
    const float* wk = (const float*)d_in[5];
    const float* bk = (const float*)d_in[6];
    const float* wv = (const float*)d_in[7];
    const float* bv = (const float*)d_in[8];
    const float* wo = (const float*)d_in[9];
    const float* bo = (const float*)d_in[10];
    float* out = (float*)d_out;

    float *qb, *kb, *vb, *attn;
    cudaGetSymbolAddress((void**)&qb,   g_q);
    cudaGetSymbolAddress((void**)&kb,   g_k);
    cudaGetSymbolAddress((void**)&vb,   g_v);
    cudaGetSymbolAddress((void**)&attn, g_attn);

    // merged Q/K/V projection GEMMs (one grid, packed waves)
    gemm_qkv<<<dim3(DM / BN, MTOK / BM, 3), 256>>>(
        query, key, value, wq, bq, wk, bk, wv, bv, qb, kb, vb);

    kv_mma<<<dim3(KVCH, 32), 128>>>();
    kv_reduce<<<dim3(32, 8), 256>>>();
    qkv_mma<<<dim3(SEQ / QROWS, 32), 256>>>();

    gemm_f16<<<dim3(DM / BN, MTOK / BM), 256>>>(attn, wo, bo, out, 0);
}